// round 2
// baseline (speedup 1.0000x reference)
#include <cuda_runtime.h>
#include <cstdint>

#define MAXN 50000
#define K_DIM 128

// Scratch (allocation-free rule: __device__ globals)
__device__ float g_dinv[MAXN];
__device__ float g_h1[(size_t)MAXN * 128];
__device__ float g_buf1[(size_t)MAXN * 128];
__device__ float g_h2[(size_t)MAXN * 64];

// ---------------- degree / normalization ----------------
__global__ void k_init_dinv(int n) {
    int i = blockIdx.x * blockDim.x + threadIdx.x;
    if (i < n) g_dinv[i] = 1.0f;  // self-loop
}

__global__ void k_count_deg(const int* __restrict__ ei, int E) {
    int i = blockIdx.x * blockDim.x + threadIdx.x;
    if (i < E) {
        int d = ei[E + i];  // dst row
        atomicAdd(&g_dinv[d], 1.0f);
    }
}

__global__ void k_finish_dinv(int n) {
    int i = blockIdx.x * blockDim.x + threadIdx.x;
    if (i < n) g_dinv[i] = rsqrtf(g_dinv[i]);
}

// ---------------- GEMM: H = X @ W ; OUT = bias + H*dinv^2 ----------------
// 256 threads = 8 warps; each warp computes 4 rows x NCOL cols.
// W lives in dynamic smem (K_DIM*NCOL floats); X rows staged in static smem.
template <int NCOL, bool RELU>
__global__ void __launch_bounds__(256) k_gemm(
    const float* __restrict__ X, const float* __restrict__ W,
    const float* __restrict__ bias, const float* __restrict__ dinv,
    float* __restrict__ H, float* __restrict__ OUT, int nrows)
{
    constexpr int CPT = NCOL / 32;  // cols per thread (4 or 2)
    extern __shared__ float sW[];                  // K_DIM * NCOL
    __shared__ float sX[8][4][K_DIM];              // 16 KB

    const int tid  = threadIdx.x;
    const int warp = tid >> 5;
    const int lane = tid & 31;

    // cooperative load of W (float4)
    const int wElems4 = K_DIM * NCOL / 4;
    for (int i = tid; i < wElems4; i += 256)
        ((float4*)sW)[i] = ((const float4*)W)[i];

    const int row0 = blockIdx.x * 32 + warp * 4;

    // stage 4 X rows per warp (one float4 per lane per row)
#pragma unroll
    for (int rr = 0; rr < 4; rr++) {
        int row = row0 + rr;
        if (row < nrows) {
            float4 v = ((const float4*)(X + (size_t)row * K_DIM))[lane];
            if (RELU) {
                v.x = fmaxf(v.x, 0.0f); v.y = fmaxf(v.y, 0.0f);
                v.z = fmaxf(v.z, 0.0f); v.w = fmaxf(v.w, 0.0f);
            }
            ((float4*)&sX[warp][rr][0])[lane] = v;
        }
    }
    __syncthreads();

    float acc[4][CPT];
#pragma unroll
    for (int r = 0; r < 4; r++)
#pragma unroll
        for (int j = 0; j < CPT; j++) acc[r][j] = 0.0f;

    float bv[CPT];
#pragma unroll
    for (int j = 0; j < CPT; j++) bv[j] = bias[lane * CPT + j];

#pragma unroll 8
    for (int k = 0; k < K_DIM; k++) {
        float w[CPT];
        if (CPT == 4) {
            float4 wv = ((const float4*)(sW + k * NCOL))[lane];
            w[0] = wv.x; w[1] = wv.y; w[2] = wv.z; w[3] = wv.w;
        } else {
            float2 wv = ((const float2*)(sW + k * NCOL))[lane];
            w[0] = wv.x; w[1] = wv.y;
        }
        float x0 = sX[warp][0][k];
        float x1 = sX[warp][1][k];
        float x2 = sX[warp][2][k];
        float x3 = sX[warp][3][k];
#pragma unroll
        for (int j = 0; j < CPT; j++) {
            acc[0][j] = fmaf(x0, w[j], acc[0][j]);
            acc[1][j] = fmaf(x1, w[j], acc[1][j]);
            acc[2][j] = fmaf(x2, w[j], acc[2][j]);
            acc[3][j] = fmaf(x3, w[j], acc[3][j]);
        }
    }

#pragma unroll
    for (int rr = 0; rr < 4; rr++) {
        int row = row0 + rr;
        if (row < nrows) {
            float di = dinv[row];
            float d2 = di * di;
#pragma unroll
            for (int j = 0; j < CPT; j++) {
                int c = lane * CPT + j;
                float h = acc[rr][j];
                H[(size_t)row * NCOL + c]   = h;
                OUT[(size_t)row * NCOL + c] = bv[j] + h * d2;
            }
        }
    }
}

// ---------------- edge aggregation: OUT[dst] += H[src] * dinv[src]*dinv[dst] ----------------
// LPE lanes per edge (32 for CH=128, 16 for CH=64), float4 per lane, vectorized red.
template <int CH>
__global__ void __launch_bounds__(256) k_edge_agg(
    const int* __restrict__ ei, const float* __restrict__ H,
    const float* __restrict__ dinv, float* __restrict__ OUT, int E)
{
    constexpr int LPE   = CH / 4;
    constexpr int SHIFT = (CH == 128) ? 5 : 4;
    int idx = blockIdx.x * blockDim.x + threadIdx.x;
    int e   = idx >> SHIFT;
    int l   = idx & (LPE - 1);
    if (e >= E) return;

    int s = ei[e];
    int d = ei[E + e];
    float nrm = dinv[s] * dinv[d];

    float4 v = *(const float4*)(H + (size_t)s * CH + l * 4);
    float a = v.x * nrm, b = v.y * nrm, c = v.z * nrm, w = v.w * nrm;
    float* o = OUT + (size_t)d * CH + l * 4;
    asm volatile("red.global.add.v4.f32 [%0], {%1, %2, %3, %4};"
                 :: "l"(o), "f"(a), "f"(b), "f"(c), "f"(w)
                 : "memory");
}

// ---------------- launch ----------------
extern "C" void kernel_launch(void* const* d_in, const int* in_sizes, int n_in,
                              void* d_out, int out_size)
{
    const float* x  = (const float*)d_in[0];
    const int*   ei = (const int*)d_in[1];   // JAX x64 disabled: edge_index is int32
    const float* W1 = (const float*)d_in[2];
    const float* b1 = (const float*)d_in[3];
    const float* W2 = (const float*)d_in[4];
    const float* b2 = (const float*)d_in[5];
    float*       out = (float*)d_out;

    const int N = in_sizes[0] / 128;   // 50000
    const int E = in_sizes[1] / 2;     // 800000

    float* dinv; cudaGetSymbolAddress((void**)&dinv, g_dinv);
    float* h1;   cudaGetSymbolAddress((void**)&h1,   g_h1);
    float* buf1; cudaGetSymbolAddress((void**)&buf1, g_buf1);
    float* h2;   cudaGetSymbolAddress((void**)&h2,   g_h2);

    cudaFuncSetAttribute((const void*)k_gemm<128, false>,
                         cudaFuncAttributeMaxDynamicSharedMemorySize, 128 * 128 * 4);
    cudaFuncSetAttribute((const void*)k_gemm<64, true>,
                         cudaFuncAttributeMaxDynamicSharedMemorySize, 128 * 64 * 4);

    // 1) normalization coefficients
    k_init_dinv<<<(N + 255) / 256, 256>>>(N);
    k_count_deg<<<(E + 255) / 256, 256>>>(ei, E);
    k_finish_dinv<<<(N + 255) / 256, 256>>>(N);

    // 2) layer 1: h1 = x@W1 ; buf1 = b1 + h1*dinv^2 (self-loop fused)
    int gblocks = (N + 31) / 32;
    k_gemm<128, false><<<gblocks, 256, 128 * 128 * 4>>>(x, W1, b1, dinv, h1, buf1, N);

    // 3) layer 1 edge scatter
    {
        long long threads = (long long)E * 32;
        int blocks = (int)((threads + 255) / 256);
        k_edge_agg<128><<<blocks, 256>>>(ei, h1, dinv, buf1, E);
    }

    // 4) layer 2: h2 = relu(buf1)@W2 ; out = b2 + h2*dinv^2
    k_gemm<64, true><<<gblocks, 256, 128 * 64 * 4>>>(buf1, W2, b2, dinv, h2, out, N);

    // 5) layer 2 edge scatter
    {
        long long threads = (long long)E * 16;
        int blocks = (int)((threads + 255) / 256);
        k_edge_agg<64><<<blocks, 256>>>(ei, h2, dinv, out, E);
    }
}

// round 3
// speedup vs baseline: 1.1371x; 1.1371x over previous
#include <cuda_runtime.h>
#include <cstdint>

#define MAXN 50000
#define K_DIM 128

// Scratch (allocation-free rule: __device__ globals)
__device__ float g_dinv[MAXN];
__device__ float g_h1[(size_t)MAXN * 128];
__device__ float g_buf1[(size_t)MAXN * 128];
__device__ float g_h2[(size_t)MAXN * 64];

// ---------------- packed f32x2 helpers ----------------
__device__ __forceinline__ unsigned long long packdup(float x) {
    unsigned long long r;
    asm("mov.b64 %0, {%1, %1};" : "=l"(r) : "f"(x));
    return r;
}
__device__ __forceinline__ void ffma2(unsigned long long& d,
                                      unsigned long long a,
                                      unsigned long long b) {
    asm("fma.rn.f32x2 %0, %1, %2, %0;" : "+l"(d) : "l"(a), "l"(b));
}
__device__ __forceinline__ unsigned long long ffma2v(unsigned long long a,
                                                     unsigned long long b,
                                                     unsigned long long c) {
    unsigned long long d;
    asm("fma.rn.f32x2 %0, %1, %2, %3;" : "=l"(d) : "l"(a), "l"(b), "l"(c));
    return d;
}

// ---------------- degree / normalization ----------------
__global__ void k_init_dinv(int n) {
    int i = blockIdx.x * blockDim.x + threadIdx.x;
    if (i < n) g_dinv[i] = 1.0f;  // self-loop
}

__global__ void k_count_deg(const int* __restrict__ ei, int E) {
    int i = blockIdx.x * blockDim.x + threadIdx.x;
    if (i < E) {
        int d = ei[E + i];  // dst row
        atomicAdd(&g_dinv[d], 1.0f);
    }
}

__global__ void k_finish_dinv(int n) {
    int i = blockIdx.x * blockDim.x + threadIdx.x;
    if (i < n) g_dinv[i] = rsqrtf(g_dinv[i]);
}

// ---------------- GEMM: H = X @ W ; OUT = bias + H*dinv^2 ----------------
// 256 threads = 8 warps; each warp computes 8 rows x NCOL cols via packed
// fma.rn.f32x2 (col-pair accumulators). W in dynamic smem, X rows in static smem.
template <int NCOL, bool RELU>
__global__ void __launch_bounds__(256) k_gemm(
    const float* __restrict__ X, const float* __restrict__ W,
    const float* __restrict__ bias, const float* __restrict__ dinv,
    float* __restrict__ H, float* __restrict__ OUT, int nrows)
{
    constexpr int P = NCOL / 64;  // u64 col-pairs per lane (2 or 1)
    extern __shared__ float sW[];                  // K_DIM * NCOL
    __shared__ float sX[8][8][K_DIM];              // 8 warps x 8 rows x 128 = 32KB

    const int tid  = threadIdx.x;
    const int warp = tid >> 5;
    const int lane = tid & 31;

    // cooperative load of W (float4)
    const int wElems4 = K_DIM * NCOL / 4;
    for (int i = tid; i < wElems4; i += 256)
        ((float4*)sW)[i] = ((const float4*)W)[i];

    const int row0 = blockIdx.x * 64 + warp * 8;

    // stage 8 X rows per warp (one float4 per lane per row)
#pragma unroll
    for (int rr = 0; rr < 8; rr++) {
        int row = row0 + rr;
        if (row < nrows) {
            float4 v = ((const float4*)(X + (size_t)row * K_DIM))[lane];
            if (RELU) {
                v.x = fmaxf(v.x, 0.0f); v.y = fmaxf(v.y, 0.0f);
                v.z = fmaxf(v.z, 0.0f); v.w = fmaxf(v.w, 0.0f);
            }
            ((float4*)&sX[warp][rr][0])[lane] = v;
        }
    }
    __syncthreads();

    unsigned long long acc[8][P];
#pragma unroll
    for (int r = 0; r < 8; r++)
#pragma unroll
        for (int j = 0; j < P; j++) acc[r][j] = 0ull;

    // bias pairs for this lane's columns
    unsigned long long bv[P];
#pragma unroll
    for (int j = 0; j < P; j++)
        bv[j] = ((const unsigned long long*)bias)[lane * P + j];

#pragma unroll 4
    for (int k = 0; k < K_DIM; k++) {
        unsigned long long w[P];
        if (P == 2) {
            ulonglong2 wv = ((const ulonglong2*)(sW + k * NCOL))[lane];
            w[0] = wv.x; w[1] = wv.y;
        } else {
            w[0] = ((const unsigned long long*)(sW + k * NCOL))[lane];
        }
#pragma unroll
        for (int r = 0; r < 8; r++) {
            unsigned long long xp = packdup(sX[warp][r][k]);
#pragma unroll
            for (int j = 0; j < P; j++) ffma2(acc[r][j], xp, w[j]);
        }
    }

#pragma unroll
    for (int rr = 0; rr < 8; rr++) {
        int row = row0 + rr;
        if (row < nrows) {
            float di = dinv[row];
            unsigned long long d2 = packdup(di * di);
            unsigned long long* hp = (unsigned long long*)(H   + (size_t)row * NCOL) + lane * P;
            unsigned long long* op = (unsigned long long*)(OUT + (size_t)row * NCOL) + lane * P;
#pragma unroll
            for (int j = 0; j < P; j++) {
                hp[j] = acc[rr][j];
                op[j] = ffma2v(acc[rr][j], d2, bv[j]);
            }
        }
    }
}

// ---------------- edge aggregation: OUT[dst] += H[src] * dinv[src]*dinv[dst] ----------------
// LPE lanes per edge (32 for CH=128, 16 for CH=64), float4 per lane, vectorized red.
template <int CH>
__global__ void __launch_bounds__(256) k_edge_agg(
    const int* __restrict__ ei, const float* __restrict__ H,
    const float* __restrict__ dinv, float* __restrict__ OUT, int E)
{
    constexpr int LPE   = CH / 4;
    constexpr int SHIFT = (CH == 128) ? 5 : 4;
    int idx = blockIdx.x * blockDim.x + threadIdx.x;
    int e   = idx >> SHIFT;
    int l   = idx & (LPE - 1);
    if (e >= E) return;

    int s = ei[e];
    int d = ei[E + e];
    float nrm = dinv[s] * dinv[d];

    float4 v = *(const float4*)(H + (size_t)s * CH + l * 4);
    float a = v.x * nrm, b = v.y * nrm, c = v.z * nrm, w = v.w * nrm;
    float* o = OUT + (size_t)d * CH + l * 4;
    asm volatile("red.global.add.v4.f32 [%0], {%1, %2, %3, %4};"
                 :: "l"(o), "f"(a), "f"(b), "f"(c), "f"(w)
                 : "memory");
}

// ---------------- launch ----------------
extern "C" void kernel_launch(void* const* d_in, const int* in_sizes, int n_in,
                              void* d_out, int out_size)
{
    const float* x  = (const float*)d_in[0];
    const int*   ei = (const int*)d_in[1];   // int32 edge list
    const float* W1 = (const float*)d_in[2];
    const float* b1 = (const float*)d_in[3];
    const float* W2 = (const float*)d_in[4];
    const float* b2 = (const float*)d_in[5];
    float*       out = (float*)d_out;

    const int N = in_sizes[0] / 128;   // 50000
    const int E = in_sizes[1] / 2;     // 800000

    float* dinv; cudaGetSymbolAddress((void**)&dinv, g_dinv);
    float* h1;   cudaGetSymbolAddress((void**)&h1,   g_h1);
    float* buf1; cudaGetSymbolAddress((void**)&buf1, g_buf1);
    float* h2;   cudaGetSymbolAddress((void**)&h2,   g_h2);

    cudaFuncSetAttribute((const void*)k_gemm<128, false>,
                         cudaFuncAttributeMaxDynamicSharedMemorySize, 128 * 128 * 4);
    cudaFuncSetAttribute((const void*)k_gemm<64, true>,
                         cudaFuncAttributeMaxDynamicSharedMemorySize, 128 * 64 * 4);

    // 1) normalization coefficients
    k_init_dinv<<<(N + 255) / 256, 256>>>(N);
    k_count_deg<<<(E + 255) / 256, 256>>>(ei, E);
    k_finish_dinv<<<(N + 255) / 256, 256>>>(N);

    // 2) layer 1: h1 = x@W1 ; buf1 = b1 + h1*dinv^2 (self-loop fused)
    int gblocks = (N + 63) / 64;
    k_gemm<128, false><<<gblocks, 256, 128 * 128 * 4>>>(x, W1, b1, dinv, h1, buf1, N);

    // 3) layer 1 edge scatter
    {
        long long threads = (long long)E * 32;
        int blocks = (int)((threads + 255) / 256);
        k_edge_agg<128><<<blocks, 256>>>(ei, h1, dinv, buf1, E);
    }

    // 4) layer 2: h2 = relu(buf1)@W2 ; out = b2 + h2*dinv^2
    k_gemm<64, true><<<gblocks, 256, 128 * 64 * 4>>>(buf1, W2, b2, dinv, h2, out, N);

    // 5) layer 2 edge scatter
    {
        long long threads = (long long)E * 16;
        int blocks = (int)((threads + 255) / 256);
        k_edge_agg<64><<<blocks, 256>>>(ei, h2, dinv, out, E);
    }
}

// round 4
// speedup vs baseline: 1.6258x; 1.4298x over previous
#include <cuda_runtime.h>
#include <cstdint>

#define MAXN 50000
#define MAXE 800000
#define K_DIM 128

// Scratch (allocation-free rule: __device__ globals)
__device__ float  g_dinv[MAXN];
__device__ int    g_deg[MAXN];
__device__ int    g_rowptr[MAXN + 1];
__device__ int    g_cursor[MAXN];
__device__ int    g_bsum[256];
__device__ int    g_boff[256];
__device__ float2 g_csr[MAXE];         // (src as int bits, norm)
__device__ float  g_h1[(size_t)MAXN * 128];
__device__ float  g_buf1[(size_t)MAXN * 128];
__device__ float  g_h2[(size_t)MAXN * 64];

// ---------------- packed f32x2 helpers ----------------
__device__ __forceinline__ unsigned long long packdup(float x) {
    unsigned long long r;
    asm("mov.b64 %0, {%1, %1};" : "=l"(r) : "f"(x));
    return r;
}
__device__ __forceinline__ void ffma2(unsigned long long& d,
                                      unsigned long long a,
                                      unsigned long long b) {
    asm("fma.rn.f32x2 %0, %1, %2, %0;" : "+l"(d) : "l"(a), "l"(b));
}
__device__ __forceinline__ unsigned long long ffma2v(unsigned long long a,
                                                     unsigned long long b,
                                                     unsigned long long c) {
    unsigned long long d;
    asm("fma.rn.f32x2 %0, %1, %2, %3;" : "=l"(d) : "l"(a), "l"(b), "l"(c));
    return d;
}
__device__ __forceinline__ unsigned long long add2(unsigned long long a,
                                                   unsigned long long b) {
    unsigned long long d;
    asm("add.rn.f32x2 %0, %1, %2;" : "=l"(d) : "l"(a), "l"(b));
    return d;
}

// ---------------- degree / normalization / CSR build ----------------
__global__ void k_zero_deg(int n) {
    int i = blockIdx.x * blockDim.x + threadIdx.x;
    if (i < n) g_deg[i] = 0;
}

__global__ void k_count_deg(const int* __restrict__ ei, int E) {
    int i = blockIdx.x * blockDim.x + threadIdx.x;
    if (i < E) atomicAdd(&g_deg[ei[E + i]], 1);
}

__global__ void k_dinv(int n) {
    int i = blockIdx.x * blockDim.x + threadIdx.x;
    if (i < n) g_dinv[i] = rsqrtf((float)g_deg[i] + 1.0f);  // +1 self-loop
}

// Block-level inclusive scan; writes per-element exclusive to rowptr, block sum to bsum.
__global__ void k_scan1(int n) {
    __shared__ int s[256];
    int t = threadIdx.x;
    int i = blockIdx.x * 256 + t;
    int v = (i < n) ? g_deg[i] : 0;
    s[t] = v;
    __syncthreads();
#pragma unroll
    for (int off = 1; off < 256; off <<= 1) {
        int a = (t >= off) ? s[t - off] : 0;
        __syncthreads();
        s[t] += a;
        __syncthreads();
    }
    if (i < n) g_rowptr[i] = s[t] - v;   // exclusive within block
    if (t == 255) g_bsum[blockIdx.x] = s[255];
}

// Exclusive scan of block sums (single block, nb <= 256).
__global__ void k_scan2(int nb) {
    __shared__ int s[256];
    int t = threadIdx.x;
    int v = (t < nb) ? g_bsum[t] : 0;
    s[t] = v;
    __syncthreads();
#pragma unroll
    for (int off = 1; off < 256; off <<= 1) {
        int a = (t >= off) ? s[t - off] : 0;
        __syncthreads();
        s[t] += a;
        __syncthreads();
    }
    if (t < nb) g_boff[t] = s[t] - v;
}

__global__ void k_scan3(int n) {
    int i = blockIdx.x * blockDim.x + threadIdx.x;
    if (i < n) {
        int r = g_rowptr[i] + g_boff[blockIdx.x];
        g_rowptr[i] = r;
        g_cursor[i] = r;
        if (i == n - 1) g_rowptr[n] = r + g_deg[i];
    }
}

__global__ void k_scatter(const int* __restrict__ ei, int E) {
    int e = blockIdx.x * blockDim.x + threadIdx.x;
    if (e < E) {
        int s = ei[e];
        int d = ei[E + e];
        int pos = atomicAdd(&g_cursor[d], 1);
        g_csr[pos] = make_float2(__int_as_float(s), g_dinv[s] * g_dinv[d]);
    }
}

// ---------------- GEMM: H = X @ W ; OUT = bias + H*dinv^2 ----------------
template <int NCOL, bool RELU>
__global__ void __launch_bounds__(256) k_gemm(
    const float* __restrict__ X, const float* __restrict__ W,
    const float* __restrict__ bias, const float* __restrict__ dinv,
    float* __restrict__ H, float* __restrict__ OUT, int nrows)
{
    constexpr int P = NCOL / 64;  // u64 col-pairs per lane (2 or 1)
    extern __shared__ float sW[];                  // K_DIM * NCOL
    __shared__ float sX[8][8][K_DIM];              // 32KB

    const int tid  = threadIdx.x;
    const int warp = tid >> 5;
    const int lane = tid & 31;

    const int wElems4 = K_DIM * NCOL / 4;
    for (int i = tid; i < wElems4; i += 256)
        ((float4*)sW)[i] = ((const float4*)W)[i];

    const int row0 = blockIdx.x * 64 + warp * 8;

#pragma unroll
    for (int rr = 0; rr < 8; rr++) {
        int row = row0 + rr;
        if (row < nrows) {
            float4 v = ((const float4*)(X + (size_t)row * K_DIM))[lane];
            if (RELU) {
                v.x = fmaxf(v.x, 0.0f); v.y = fmaxf(v.y, 0.0f);
                v.z = fmaxf(v.z, 0.0f); v.w = fmaxf(v.w, 0.0f);
            }
            ((float4*)&sX[warp][rr][0])[lane] = v;
        }
    }
    __syncthreads();

    unsigned long long acc[8][P];
#pragma unroll
    for (int r = 0; r < 8; r++)
#pragma unroll
        for (int j = 0; j < P; j++) acc[r][j] = 0ull;

    unsigned long long bv[P];
#pragma unroll
    for (int j = 0; j < P; j++)
        bv[j] = ((const unsigned long long*)bias)[lane * P + j];

#pragma unroll 8
    for (int k = 0; k < K_DIM; k++) {
        unsigned long long w[P];
        if (P == 2) {
            ulonglong2 wv = ((const ulonglong2*)(sW + k * NCOL))[lane];
            w[0] = wv.x; w[1] = wv.y;
        } else {
            w[0] = ((const unsigned long long*)(sW + k * NCOL))[lane];
        }
#pragma unroll
        for (int r = 0; r < 8; r++) {
            unsigned long long xp = packdup(sX[warp][r][k]);
#pragma unroll
            for (int j = 0; j < P; j++) ffma2(acc[r][j], xp, w[j]);
        }
    }

#pragma unroll
    for (int rr = 0; rr < 8; rr++) {
        int row = row0 + rr;
        if (row < nrows) {
            float di = dinv[row];
            unsigned long long d2 = packdup(di * di);
            unsigned long long* hp = (unsigned long long*)(H   + (size_t)row * NCOL) + lane * P;
            unsigned long long* op = (unsigned long long*)(OUT + (size_t)row * NCOL) + lane * P;
#pragma unroll
            for (int j = 0; j < P; j++) {
                hp[j] = acc[rr][j];
                op[j] = ffma2v(acc[rr][j], d2, bv[j]);
            }
        }
    }
}

// ---------------- CSR aggregation: OUT[n] += sum_{e in row n} H[src_e] * nrm_e ----------------
// One warp per node, 128 channels = 1 float4 (2 f32x2 pairs) per lane. No atomics.
__global__ void __launch_bounds__(256) k_agg128(
    const float* __restrict__ H, float* __restrict__ OUT, int N)
{
    int gw   = (blockIdx.x * 256 + threadIdx.x) >> 5;
    int lane = threadIdx.x & 31;
    if (gw >= N) return;
    int beg = g_rowptr[gw], end = g_rowptr[gw + 1];
    if (beg == end) return;

    const float* Hl = H + lane * 4;
    unsigned long long a0 = 0ull, a1 = 0ull;

    int j = beg;
    for (; j + 2 <= end; j += 2) {
        float2 e0 = g_csr[j];
        float2 e1 = g_csr[j + 1];
        ulonglong2 v0 = *(const ulonglong2*)(Hl + (size_t)__float_as_int(e0.x) * 128);
        ulonglong2 v1 = *(const ulonglong2*)(Hl + (size_t)__float_as_int(e1.x) * 128);
        unsigned long long n0 = packdup(e0.y);
        unsigned long long n1 = packdup(e1.y);
        a0 = ffma2v(v0.x, n0, a0); a1 = ffma2v(v0.y, n0, a1);
        a0 = ffma2v(v1.x, n1, a0); a1 = ffma2v(v1.y, n1, a1);
    }
    if (j < end) {
        float2 e0 = g_csr[j];
        ulonglong2 v0 = *(const ulonglong2*)(Hl + (size_t)__float_as_int(e0.x) * 128);
        unsigned long long n0 = packdup(e0.y);
        a0 = ffma2v(v0.x, n0, a0); a1 = ffma2v(v0.y, n0, a1);
    }

    ulonglong2* op = (ulonglong2*)(OUT + (size_t)gw * 128 + lane * 4);
    ulonglong2 ob = *op;
    ob.x = add2(ob.x, a0);
    ob.y = add2(ob.y, a1);
    *op = ob;
}

// Half-warp (16 lanes) per node, 64 channels = 1 float4 per lane.
__global__ void __launch_bounds__(256) k_agg64(
    const float* __restrict__ H, float* __restrict__ OUT, int N)
{
    int idx  = blockIdx.x * 256 + threadIdx.x;
    int node = idx >> 4;
    int lane = idx & 15;
    if (node >= N) return;
    int beg = g_rowptr[node], end = g_rowptr[node + 1];
    if (beg == end) return;

    const float* Hl = H + lane * 4;
    unsigned long long a0 = 0ull, a1 = 0ull;

    int j = beg;
    for (; j + 2 <= end; j += 2) {
        float2 e0 = g_csr[j];
        float2 e1 = g_csr[j + 1];
        ulonglong2 v0 = *(const ulonglong2*)(Hl + (size_t)__float_as_int(e0.x) * 64);
        ulonglong2 v1 = *(const ulonglong2*)(Hl + (size_t)__float_as_int(e1.x) * 64);
        unsigned long long n0 = packdup(e0.y);
        unsigned long long n1 = packdup(e1.y);
        a0 = ffma2v(v0.x, n0, a0); a1 = ffma2v(v0.y, n0, a1);
        a0 = ffma2v(v1.x, n1, a0); a1 = ffma2v(v1.y, n1, a1);
    }
    if (j < end) {
        float2 e0 = g_csr[j];
        ulonglong2 v0 = *(const ulonglong2*)(Hl + (size_t)__float_as_int(e0.x) * 64);
        unsigned long long n0 = packdup(e0.y);
        a0 = ffma2v(v0.x, n0, a0); a1 = ffma2v(v0.y, n0, a1);
    }

    ulonglong2* op = (ulonglong2*)(OUT + (size_t)node * 64 + lane * 4);
    ulonglong2 ob = *op;
    ob.x = add2(ob.x, a0);
    ob.y = add2(ob.y, a1);
    *op = ob;
}

// ---------------- launch ----------------
extern "C" void kernel_launch(void* const* d_in, const int* in_sizes, int n_in,
                              void* d_out, int out_size)
{
    const float* x  = (const float*)d_in[0];
    const int*   ei = (const int*)d_in[1];   // int32 edge list
    const float* W1 = (const float*)d_in[2];
    const float* b1 = (const float*)d_in[3];
    const float* W2 = (const float*)d_in[4];
    const float* b2 = (const float*)d_in[5];
    float*       out = (float*)d_out;

    const int N = in_sizes[0] / 128;   // 50000
    const int E = in_sizes[1] / 2;     // 800000

    float* dinv; cudaGetSymbolAddress((void**)&dinv, g_dinv);
    float* h1;   cudaGetSymbolAddress((void**)&h1,   g_h1);
    float* buf1; cudaGetSymbolAddress((void**)&buf1, g_buf1);
    float* h2;   cudaGetSymbolAddress((void**)&h2,   g_h2);

    cudaFuncSetAttribute((const void*)k_gemm<128, false>,
                         cudaFuncAttributeMaxDynamicSharedMemorySize, 128 * 128 * 4);
    cudaFuncSetAttribute((const void*)k_gemm<64, true>,
                         cudaFuncAttributeMaxDynamicSharedMemorySize, 128 * 64 * 4);

    const int nblkN = (N + 255) / 256;   // 196
    const int nblkE = (E + 255) / 256;

    // CSR build (counting sort by dst) + normalization
    k_zero_deg<<<nblkN, 256>>>(N);
    k_count_deg<<<nblkE, 256>>>(ei, E);
    k_dinv<<<nblkN, 256>>>(N);
    k_scan1<<<nblkN, 256>>>(N);
    k_scan2<<<1, 256>>>(nblkN);
    k_scan3<<<nblkN, 256>>>(N);
    k_scatter<<<nblkE, 256>>>(ei, E);

    // layer 1: h1 = x@W1 ; buf1 = b1 + h1*dinv^2 (self-loop fused)
    int gblocks = (N + 63) / 64;
    k_gemm<128, false><<<gblocks, 256, 128 * 128 * 4>>>(x, W1, b1, dinv, h1, buf1, N);
    k_agg128<<<(N * 32 + 255) / 256, 256>>>(h1, buf1, N);

    // layer 2: h2 = relu(buf1)@W2 ; out = b2 + h2*dinv^2
    k_gemm<64, true><<<gblocks, 256, 128 * 64 * 4>>>(buf1, W2, b2, dinv, h2, out, N);
    k_agg64<<<(N * 16 + 255) / 256, 256>>>(h2, out, N);
}